// round 16
// baseline (speedup 1.0000x reference)
#include <cuda_runtime.h>

// Problem constants (fixed by the reference):
//   x:    (B=32, T=1024, N=512, C=3) float32, innermost stride 1 over C
//   perm: (B, NB=512) int32, per-batch block permutation (PS=2, NB=T/PS)
// out[b,t,n,0] = x[b, perm[b, t/PS]*PS + t%PS, n, 0]
// out[b,t,n,c] = x[b, t, n, c]  for c in {1,2}
static constexpr int Bdim = 32;
static constexpr int Tdim = 1024;
static constexpr int Ndim = 512;
static constexpr int Cdim = 3;
static constexpr int PS   = 2;
static constexpr int NB   = Tdim / PS;              // 512
static constexpr unsigned TOTAL_PTS = (unsigned)Bdim * Tdim * Ndim;  // 16,777,216

__global__ void __launch_bounds__(256)
patch_perm_kernel(const float* __restrict__ x,
                  const int*   __restrict__ perm,
                  float*       __restrict__ out)
{
    unsigned p = blockIdx.x * blockDim.x + threadIdx.x;
    if (p >= TOTAL_PTS) return;

    // Decompose p -> (b, t, n). All divisors are powers of two -> shifts.
    unsigned n  = p & (Ndim - 1);
    unsigned bt = p >> 9;                 // p / 512
    unsigned t  = bt & (Tdim - 1);
    unsigned b  = bt >> 10;               // bt / 1024

    // Gather source row for channel 0 (uniform across the warp: same b,t).
    int tsrc = __ldg(&perm[b * NB + (t >> 1)]) * PS + (int)(t & 1u);

    unsigned dst  = p * 3u;                                    // (b,t,n)*C
    unsigned src0 = (((b * Tdim + (unsigned)tsrc) * Ndim) + n) * 3u;

    out[dst + 0] = __ldg(&x[src0]);
    out[dst + 1] = __ldg(&x[dst + 1]);
    out[dst + 2] = __ldg(&x[dst + 2]);
}

extern "C" void kernel_launch(void* const* d_in, const int* in_sizes, int n_in,
                              void* d_out, int out_size)
{
    const float* x    = (const float*)d_in[0];
    const int*   perm = (const int*)  d_in[1];
    float*       out  = (float*)d_out;

    const int threads = 256;
    const int blocks  = (TOTAL_PTS + threads - 1) / threads;   // 65536
    patch_perm_kernel<<<blocks, threads>>>(x, perm, out);
}

// round 17
// speedup vs baseline: 1.3290x; 1.3290x over previous
#include <cuda_runtime.h>

// x: (B=32, T=1024, N=512, C=3) fp32; perm: (B, NB=512) int32; PS=2.
// out[b,t,n,0] = x[b, perm[b,t/2]*2 + t%2, n, 0]; out[b,t,n,1:2] = x[b,t,n,1:2].
//
// Vectorized view: each (b,t) row is 1536 contiguous floats = 384 float4.
// Global float4 index v: row = v/384, j = v%384. Since 1536 % 3 == 0, the
// channel of float-lane i in float4 j is (4j+i) % 3, i.e. determined by j%3:
//   j%3==0 -> ch0 lanes {x (i=0), w (i=3)}
//   j%3==1 -> ch0 lane  {z (i=2)}
//   j%3==2 -> ch0 lane  {y (i=1)}
// Patch those lanes from the source row at the SAME intra-row float offset.

static constexpr int Bdim = 32;
static constexpr int Tdim = 1024;
static constexpr int NB   = 512;                       // T / PS
static constexpr int ROW_F  = 1536;                    // N*C floats per row
static constexpr int ROW_V4 = ROW_F / 4;               // 384 float4 per row
static constexpr unsigned TOTAL_V4 = (unsigned)Bdim * Tdim * ROW_V4;  // 12,582,912

__global__ void __launch_bounds__(256)
patch_perm_v4_kernel(const float4* __restrict__ x4,
                     const float*  __restrict__ x,
                     const int*    __restrict__ perm,
                     float4*       __restrict__ out4)
{
    unsigned v = blockIdx.x * blockDim.x + threadIdx.x;   // grid sized exactly

    unsigned row = v / ROW_V4;                 // umulhi sequence
    unsigned j   = v - row * ROW_V4;           // float4 index within row
    unsigned t   = row & (Tdim - 1);
    unsigned b   = row >> 10;

    // Warp-uniform: each warp covers 32 consecutive v in one row (384 % 32 == 0).
    int tsrc = __ldg(&perm[(b << 9) + (t >> 1)]) * 2 + (int)(t & 1u);

    float4 c = __ldg(&x4[v]);                  // coalesced 16B copy load

    if (tsrc != (int)t) {                      // warp-uniform branch (~25% taken)
        unsigned srcbase = ((b << 10) + (unsigned)tsrc) * ROW_F;  // src row start (floats)
        unsigned m  = j - (j / 3u) * 3u;       // j % 3
        unsigned i0 = (3u - m) & (m ? 3u : 0u);// (3 - j%3) % 3 : 0->0, 1->2, 2->1
        // branch-free form of (3-m)%3 without division quirks:
        i0 = (m == 0u) ? 0u : 3u - m;

        unsigned e0 = j * 4u + i0;             // intra-row float offset of first ch0 lane
        float g0 = __ldg(&x[srcbase + e0]);
        // second ch0 lane exists only when i0==0 (lanes 0 and 3); e0+3 stays
        // in-row there (max j with j%3==0 is 381 -> e0+3 = 1527 < 1536).
        float g1 = __ldg(&x[srcbase + e0 + ((i0 == 0u) ? 3u : 0u)]);

        c.x = (i0 == 0u) ? g0 : c.x;
        c.y = (i0 == 1u) ? g0 : c.y;
        c.z = (i0 == 2u) ? g0 : c.z;
        c.w = (i0 == 0u) ? g1 : c.w;
    }

    out4[v] = c;                               // coalesced 16B store
}

extern "C" void kernel_launch(void* const* d_in, const int* in_sizes, int n_in,
                              void* d_out, int out_size)
{
    const float* x    = (const float*)d_in[0];
    const int*   perm = (const int*)  d_in[1];

    const int threads = 256;
    const int blocks  = TOTAL_V4 / threads;    // 49,152 exactly
    patch_perm_v4_kernel<<<blocks, threads>>>((const float4*)x, x, perm,
                                              (float4*)d_out);
}